// round 11
// baseline (speedup 1.0000x reference)
#include <cuda_runtime.h>

// LSTMForecastModel: B=4096, T=128, OUT=64, H=200.
// R10: R7 skeleton (unit-pair weights, coalesced 2xLDG.128/k) +
//  (a) h stored DUPLICATED in smem -> LDS.128 yields f32x2 pairs, zero MOVs/k
//  (b) manual double-buffered k-loop (prefetch k+1/k+2 while computing k)
//  (c) parallel decoder linear head.

#define BATCH  4096
#define TLEN   128
#define OUTLEN 64
#define HID    200
#define G4     800
#define MCTA   32
#define NTHR   800      // 100 unit-pairs (txp) * 8 row-blocks (ty, 4 rows)
#define NBLK   128
#define WSZ    (HID * G4)    // 160000
#define WPAD   (WSZ + G4)    // +1 k-row so distance-2 prefetch never faults

typedef unsigned long long u64;

// Paired weights (as R7): [k*800 + txp*8 + g*2 + half], g=(i,f,g,o), half0=unit txp, half1=unit txp+100.
// 0=enc_Whh0 1=enc_Wih1 2=enc_Whh1 3=dec_Whh0 4=dec_Wih1 5=dec_Whh1
__device__ float g_W[6][WPAD];
// Paired vectors [txp*8 + g*2 + half]: 0=enc_Wih0 1=enc_b0 2=enc_b1 3=dec_Wih0 4=dec_b0 5=dec_b1
__device__ float g_v[6][G4];

__global__ void prep_kernel(const float* __restrict__ eWhh0, const float* __restrict__ eWih1,
                            const float* __restrict__ eWhh1, const float* __restrict__ dWhh0,
                            const float* __restrict__ dWih1, const float* __restrict__ dWhh1,
                            const float* __restrict__ eWih0, const float* __restrict__ eb0,
                            const float* __restrict__ eb1,  const float* __restrict__ dWih0,
                            const float* __restrict__ db0,  const float* __restrict__ db1)
{
    int i = blockIdx.x * blockDim.x + threadIdx.x;
    if (i < WSZ) {
        int k    = i / G4;
        int rest = i - k * G4;
        int txp  = rest >> 3;
        int q    = rest & 7;
        int g    = q >> 1;
        int u    = txp + (q & 1) * 100;
        int s = (g * HID + u) * HID + k;
        g_W[0][i] = eWhh0[s];
        g_W[1][i] = eWih1[s];
        g_W[2][i] = eWhh1[s];
        g_W[3][i] = dWhh0[s];
        g_W[4][i] = dWih1[s];
        g_W[5][i] = dWhh1[s];
    }
    if (i < G4) {
        int txp = i >> 3, q = i & 7;
        int g = q >> 1;
        int u = txp + (q & 1) * 100;
        int s = g * HID + u;
        g_v[0][i] = eWih0[s];
        g_v[1][i] = eb0[s];
        g_v[2][i] = eb1[s];
        g_v[3][i] = dWih0[s];
        g_v[4][i] = db0[s];
        g_v[5][i] = db1[s];
    }
}

// ---- packed f32x2 primitives ----
__device__ __forceinline__ void fma2(u64& d, u64 a, u64 b) {
    asm("fma.rn.f32x2 %0, %1, %2, %0;" : "+l"(d) : "l"(a), "l"(b));
}
__device__ __forceinline__ u64 dup2(float w) {
    u64 r;
    asm("mov.b64 %0, {%1, %1};" : "=l"(r) : "f"(w));
    return r;
}
__device__ __forceinline__ u64 pk2(float lo, float hi) {
    u64 r;
    asm("mov.b64 %0, {%1, %2};" : "=l"(r) : "f"(lo), "f"(hi));
    return r;
}
__device__ __forceinline__ float2 unpk(u64 v) {
    float lo, hi;
    asm("mov.b64 {%0, %1}, %2;" : "=f"(lo), "=f"(hi) : "l"(v));
    return make_float2(lo, hi);
}

__device__ __forceinline__ float sigf(float x)   { return __fdividef(1.f, 1.f + __expf(-x)); }
__device__ __forceinline__ float tanh_f(float x) { return 1.f - __fdividef(2.f, 1.f + __expf(2.f * x)); }

// acc[g][r]: pair = (unit txp, unit txp+100), r = row within 4-row block.
__device__ __forceinline__ void acc_init2(u64 acc[4][4], const float* __restrict__ vbase, int txp)
{
    const ulonglong2* b2 = reinterpret_cast<const ulonglong2*>(vbase) + txp * 2;
    ulonglong2 bv1 = b2[0];   // (i pair, f pair)
    ulonglong2 bv2 = b2[1];   // (g pair, o pair)
#pragma unroll
    for (int r = 0; r < 4; r++) {
        acc[0][r] = bv1.x; acc[1][r] = bv1.y; acc[2][r] = bv2.x; acc[3][r] = bv2.y;
    }
}

__device__ __forceinline__ void fma_blk(u64 acc[4][4], ulonglong2 wv1, ulonglong2 wv2,
                                        ulonglong2 hA, ulonglong2 hB)
{
    // hA.x=(r0,r0) hA.y=(r1,r1) hB.x=(r2,r2) hB.y=(r3,r3)
    fma2(acc[0][0], wv1.x, hA.x); fma2(acc[1][0], wv1.y, hA.x);
    fma2(acc[2][0], wv2.x, hA.x); fma2(acc[3][0], wv2.y, hA.x);
    fma2(acc[0][1], wv1.x, hA.y); fma2(acc[1][1], wv1.y, hA.y);
    fma2(acc[2][1], wv2.x, hA.y); fma2(acc[3][1], wv2.y, hA.y);
    fma2(acc[0][2], wv1.x, hB.x); fma2(acc[1][2], wv1.y, hB.x);
    fma2(acc[2][2], wv2.x, hB.x); fma2(acc[3][2], wv2.y, hB.x);
    fma2(acc[0][3], wv1.x, hB.y); fma2(acc[1][3], wv1.y, hB.y);
    fma2(acc[2][3], wv2.x, hB.y); fma2(acc[3][3], wv2.y, hB.y);
}

__device__ __forceinline__ void acc_rank1_2(u64 acc[4][4], const float* __restrict__ wx,
                                            int txp, u64 x0, u64 x1, u64 x2, u64 x3)
{
    const ulonglong2* b = reinterpret_cast<const ulonglong2*>(wx) + txp * 2;
    ulonglong2 w1 = b[0], w2 = b[1];
    ulonglong2 hA; hA.x = x0; hA.y = x1;
    ulonglong2 hB; hB.x = x2; hB.y = x3;
    fma_blk(acc, w1, w2, hA, hB);
}

// gates += h @ W^T. W paired [k][txp][8] (2 x ulonglong2 per (k,txp)).
// hd = DUPLICATED h: [k][64 floats] = per row the value twice -> 16 ulonglong2 per k.
// Double-buffered: prefetch k+1 / k+2 before consuming k. Tail prefetch reads
// one k-row past the end (padded in g_W; smem overrun lands in adjacent regions).
__device__ __forceinline__ void gemm_pass2(const float* __restrict__ W, const float* __restrict__ hd,
                                           int txp, int ty, u64 acc[4][4])
{
    const ulonglong2* __restrict__ w2 = reinterpret_cast<const ulonglong2*>(W) + txp * 2;
    const ulonglong2* __restrict__ h2 = reinterpret_cast<const ulonglong2*>(hd) + ty * 2;

    ulonglong2 wa0 = w2[0],  wa1 = w2[1];
    ulonglong2 ha0 = h2[0],  ha1 = h2[1];
#pragma unroll 1
    for (int k = 0; k < HID; k += 2) {
        ulonglong2 wb0 = w2[(k + 1) * 200];
        ulonglong2 wb1 = w2[(k + 1) * 200 + 1];
        ulonglong2 hb0 = h2[(k + 1) * 16];
        ulonglong2 hb1 = h2[(k + 1) * 16 + 1];
        fma_blk(acc, wa0, wa1, ha0, ha1);
        wa0 = w2[(k + 2) * 200];
        wa1 = w2[(k + 2) * 200 + 1];
        ha0 = h2[(k + 2) * 16];
        ha1 = h2[(k + 2) * 16 + 1];
        fma_blk(acc, wb0, wb1, hb0, hb1);
    }
}

// c-state in smem as u64 (unitA,unitB) pairs: index txp*32 + ty*4 + r.
// h written DUPLICATED: [unit][64] with row r at floats (2r, 2r+1).
__device__ __forceinline__ void cell_epi2(u64 acc[4][4], float* __restrict__ cs,
                                          float* __restrict__ hdst, int txp, int ty)
{
    u64* cp = reinterpret_cast<u64*>(cs) + txp * 32 + ty * 4;
    float hA[4], hB[4];
#pragma unroll
    for (int r = 0; r < 4; r++) {
        float2 iv = unpk(acc[0][r]);
        float2 fv = unpk(acc[1][r]);
        float2 gv = unpk(acc[2][r]);
        float2 ov = unpk(acc[3][r]);
        float2 cv = unpk(cp[r]);
        float cA = sigf(fv.x) * cv.x + sigf(iv.x) * tanh_f(gv.x);
        float cB = sigf(fv.y) * cv.y + sigf(iv.y) * tanh_f(gv.y);
        cp[r] = pk2(cA, cB);
        hA[r] = sigf(ov.x) * tanh_f(cA);
        hB[r] = sigf(ov.y) * tanh_f(cB);
    }
    float* dA = hdst + txp * 64 + ty * 8;
    float* dB = hdst + (txp + 100) * 64 + ty * 8;
    *reinterpret_cast<float4*>(dA)     = make_float4(hA[0], hA[0], hA[1], hA[1]);
    *reinterpret_cast<float4*>(dA + 4) = make_float4(hA[2], hA[2], hA[3], hA[3]);
    *reinterpret_cast<float4*>(dB)     = make_float4(hB[0], hB[0], hB[1], hB[1]);
    *reinterpret_cast<float4*>(dB + 4) = make_float4(hB[2], hB[2], hB[3], hB[3]);
}

// smem (floats): h0d 12800 | h1d 12800 | c0 6400 | c1 6400 | xs 4096 | vb 4800 |
//                lin 200 | inp 32 | part 256  = 47784 floats (191,136 B)
#define SMEM_FLOATS 47784

__global__ void __launch_bounds__(NTHR, 1)
lstm_kernel(const float* __restrict__ x, const float* __restrict__ linW,
            const float* __restrict__ linb, float* __restrict__ out)
{
    extern __shared__ float sm[];
    float* h0d   = sm;            // dup'd [k=200][64]
    float* h1d   = sm + 12800;
    float* c0s   = sm + 25600;
    float* c1s   = sm + 32000;
    float* xs    = sm + 38400;    // [t=128][row=32]
    float* vb    = sm + 42496;    // 6 x 800
    float* lin_s = sm + 47296;    // 200
    float* inp_s = sm + 47496;    // 32
    float* part  = sm + 47528;    // 8 x 32

    const int tid  = threadIdx.x;
    const int ty   = tid & 7;     // row-block of 4 rows
    const int txp  = tid >> 3;    // unit-pair 0..99 (units txp, txp+100)
    const int row0 = blockIdx.x * MCTA;

    // stage / init
    for (int i = tid; i < 38400; i += NTHR) sm[i] = 0.f;   // h0d,h1d,c0,c1
    for (int i = tid; i < TLEN * MCTA; i += NTHR) {
        int t = i >> 5, r = i & 31;
        xs[i] = x[(row0 + r) * TLEN + t];
    }
    {
        const float* gv = &g_v[0][0];
        for (int i = tid; i < 6 * G4; i += NTHR) vb[i] = gv[i];
    }
    for (int i = tid; i < HID; i += NTHR) lin_s[i] = linW[i];
    __syncthreads();

    const float* wx0  = vb;
    const float* b0   = vb + 800;
    const float* b1   = vb + 1600;
    const float* dwx0 = vb + 2400;
    const float* db0  = vb + 3200;
    const float* db1  = vb + 4000;

    // ---------------- encoder: 128 steps ----------------
    for (int t = 0; t < TLEN; t++) {
        u64 acc[4][4];
        acc_init2(acc, b0, txp);
        {
            float4 xv = *reinterpret_cast<const float4*>(xs + t * MCTA + ty * 4);
            acc_rank1_2(acc, wx0, txp, dup2(xv.x), dup2(xv.y), dup2(xv.z), dup2(xv.w));
        }
        gemm_pass2(g_W[0], h0d, txp, ty, acc);
        __syncthreads();
        cell_epi2(acc, c0s, h0d, txp, ty);
        __syncthreads();

        u64 accb[4][4];
        acc_init2(accb, b1, txp);
        gemm_pass2(g_W[1], h0d, txp, ty, accb);
        gemm_pass2(g_W[2], h1d, txp, ty, accb);
        __syncthreads();
        cell_epi2(accb, c1s, h1d, txp, ty);
        __syncthreads();
    }

    // decoder initial input = x[:, T-1]
    if (tid < MCTA) inp_s[tid] = xs[(TLEN - 1) * MCTA + tid];
    __syncthreads();

    const float lb = linb[0];

    // ---------------- decoder: 64 steps ----------------
    for (int t = 0; t < OUTLEN; t++) {
        u64 acc[4][4];
        acc_init2(acc, db0, txp);
        {
            float4 xv = *reinterpret_cast<const float4*>(inp_s + ty * 4);
            acc_rank1_2(acc, dwx0, txp, dup2(xv.x), dup2(xv.y), dup2(xv.z), dup2(xv.w));
        }
        gemm_pass2(g_W[3], h0d, txp, ty, acc);
        __syncthreads();
        cell_epi2(acc, c0s, h0d, txp, ty);
        __syncthreads();

        u64 accb[4][4];
        acc_init2(accb, db1, txp);
        gemm_pass2(g_W[4], h0d, txp, ty, accb);   // input = new h0
        gemm_pass2(g_W[5], h1d, txp, ty, accb);
        __syncthreads();
        cell_epi2(accb, c1s, h1d, txp, ty);
        __syncthreads();

        // linear head: pred = h1 @ lin_W.T + lin_b (8 groups x 25 units, 256 threads)
        if (tid < 256) {
            int grp = tid >> 5, r = tid & 31;
            int ub = grp * 25;
            float s = 0.f;
#pragma unroll 5
            for (int u = 0; u < 25; u++) s += lin_s[ub + u] * h1d[(ub + u) * 64 + r * 2];
            part[grp * 32 + r] = s;
        }
        __syncthreads();
        if (tid < MCTA) {
            float s = lb;
#pragma unroll
            for (int g = 0; g < 8; g++) s += part[g * 32 + tid];
            out[(row0 + tid) * OUTLEN + t] = s;
            inp_s[tid] = s;
        }
        __syncthreads();
    }
}

extern "C" void kernel_launch(void* const* d_in, const int* in_sizes, int n_in,
                              void* d_out, int out_size)
{
    (void)in_sizes; (void)n_in; (void)out_size;
    const float* x     = (const float*)d_in[0];
    const float* eWih0 = (const float*)d_in[1];
    const float* eWhh0 = (const float*)d_in[2];
    const float* eb0   = (const float*)d_in[3];
    const float* eWih1 = (const float*)d_in[4];
    const float* eWhh1 = (const float*)d_in[5];
    const float* eb1   = (const float*)d_in[6];
    const float* dWih0 = (const float*)d_in[7];
    const float* dWhh0 = (const float*)d_in[8];
    const float* db0   = (const float*)d_in[9];
    const float* dWih1 = (const float*)d_in[10];
    const float* dWhh1 = (const float*)d_in[11];
    const float* db1   = (const float*)d_in[12];
    const float* linW  = (const float*)d_in[13];
    const float* linb  = (const float*)d_in[14];
    float* out = (float*)d_out;

    cudaFuncSetAttribute(lstm_kernel, cudaFuncAttributeMaxDynamicSharedMemorySize,
                         SMEM_FLOATS * (int)sizeof(float));

    prep_kernel<<<(WSZ + 255) / 256, 256>>>(eWhh0, eWih1, eWhh1, dWhh0, dWih1, dWhh1,
                                            eWih0, eb0, eb1, dWih0, db0, db1);
    lstm_kernel<<<NBLK, NTHR, SMEM_FLOATS * (int)sizeof(float)>>>(x, linW, linb, out);
}

// round 12
// speedup vs baseline: 5.1507x; 5.1507x over previous
#include <cuda_runtime.h>
#include <cuda_bf16.h>

// LSTMForecastModel: B=4096, T=128, OUT=64, H=200.
// R11: tensor cores via mma.sync.m16n8k16 (bf16 x3 split precision, fp32 accum).
// 128 CTAs x 32 rows; 640 threads = 20 warps; warp owns 40 N-cols (10 units,
// col = unit*4 + gate). A = h in smem bf16 hi/lo (ldmatrix.x4); B pre-packed in
// gmem in per-lane fragment order (uint4 = {Bhi k01, Bhi k89, Blo k01, Blo k89});
// c-state fp32 in smem; cell epilogue pairs (i,f)/(g,o) threads via shfl_xor(1).

#define BATCH  4096
#define TLEN   128
#define OUTLEN 64
#define HID    200
#define MCTA   32
#define NTHR   640
#define NBLK   128
#define KSTEPS 13            // 13*16 = 208 >= 200 (zero padded)
#define NTILES 100           // 800 / 8
#define FRAG_ELEMS (KSTEPS * NTILES * 32)
#define ASTR   216           // A row stride in bf16 elems (432 B, conflict-free)
#define ABUF_B (32 * ASTR * 2)   // 13824 bytes per A buffer

typedef unsigned int u32;

// B fragments, per matrix: [s][jt][lane] -> uint4.
// 0=enc_Whh0 1=enc_Wih1 2=enc_Whh1 3=dec_Whh0 4=dec_Wih1 5=dec_Whh1
__device__ uint4 g_Bf[6][FRAG_ELEMS];
// vectors indexed by col n = u*4+g: 0=enc_Wih0 1=enc_b0 2=enc_b1 3=dec_Wih0 4=dec_b0 5=dec_b1
__device__ float g_v[6][800];

__device__ __forceinline__ void bsplit(float w, u32& hi, u32& lo) {
    __nv_bfloat16 h = __float2bfloat16(w);
    __nv_bfloat16 l = __float2bfloat16(w - __bfloat162float(h));
    hi = (u32)__bfloat16_as_ushort(h);
    lo = (u32)__bfloat16_as_ushort(l);
}

__global__ void prep_kernel(const float* __restrict__ eWhh0, const float* __restrict__ eWih1,
                            const float* __restrict__ eWhh1, const float* __restrict__ dWhh0,
                            const float* __restrict__ dWih1, const float* __restrict__ dWhh1,
                            const float* __restrict__ eWih0, const float* __restrict__ eb0,
                            const float* __restrict__ eb1,  const float* __restrict__ dWih0,
                            const float* __restrict__ db0,  const float* __restrict__ db1)
{
    int idx = blockIdx.x * blockDim.x + threadIdx.x;
    if (idx < FRAG_ELEMS) {
        int lane = idx & 31;
        int sj   = idx >> 5;
        int jt   = sj % NTILES;      // n-tile 0..99
        int s    = sj / NTILES;      // k-step 0..12
        int gid  = lane >> 2, tig = lane & 3;
        int n = jt * 8 + gid;        // global col
        int u = n >> 2, g = n & 3;   // unit, gate(i,f,g,o)
        int R = g * HID + u;         // source row in (4H,H)
        int k0 = s * 16 + tig * 2;
        const float* srcs[6] = {eWhh0, eWih1, eWhh1, dWhh0, dWih1, dWhh1};
#pragma unroll
        for (int m = 0; m < 6; m++) {
            const float* src = srcs[m] + R * HID;
            float w00 = (k0     < HID) ? src[k0]     : 0.f;
            float w01 = (k0 + 1 < HID) ? src[k0 + 1] : 0.f;
            float w10 = (k0 + 8 < HID) ? src[k0 + 8] : 0.f;
            float w11 = (k0 + 9 < HID) ? src[k0 + 9] : 0.f;
            u32 h00, l00, h01, l01, h10, l10, h11, l11;
            bsplit(w00, h00, l00); bsplit(w01, h01, l01);
            bsplit(w10, h10, l10); bsplit(w11, h11, l11);
            uint4 v;
            v.x = h00 | (h01 << 16);   // B_hi, k0/k0+1 (low half = lower k)
            v.y = h10 | (h11 << 16);   // B_hi, k0+8/k0+9
            v.z = l00 | (l01 << 16);   // B_lo
            v.w = l10 | (l11 << 16);
            g_Bf[m][idx] = v;
        }
    }
    if (idx < 800) {
        int u = idx >> 2, g = idx & 3;
        int sI = g * HID + u;
        g_v[0][idx] = eWih0[sI];
        g_v[1][idx] = eb0[sI];
        g_v[2][idx] = eb1[sI];
        g_v[3][idx] = dWih0[sI];
        g_v[4][idx] = db0[sI];
        g_v[5][idx] = db1[sI];
    }
}

// ---- device primitives ----
__device__ __forceinline__ u32 smem_u32(const void* p) {
    u32 a;
    asm("{ .reg .u64 t; cvta.to.shared.u64 t, %1; cvt.u32.u64 %0, t; }" : "=r"(a) : "l"(p));
    return a;
}
__device__ __forceinline__ void ldsm4(u32 (&d)[4], u32 addr) {
    asm volatile("ldmatrix.sync.aligned.m8n8.x4.shared.b16 {%0,%1,%2,%3}, [%4];"
                 : "=r"(d[0]), "=r"(d[1]), "=r"(d[2]), "=r"(d[3]) : "r"(addr));
}
__device__ __forceinline__ void mma16816(float (&c)[4], const u32 (&a)[4], u32 b0, u32 b1) {
    asm volatile("mma.sync.aligned.m16n8k16.row.col.f32.bf16.bf16.f32 "
                 "{%0,%1,%2,%3},{%4,%5,%6,%7},{%8,%9},{%0,%1,%2,%3};"
                 : "+f"(c[0]), "+f"(c[1]), "+f"(c[2]), "+f"(c[3])
                 : "r"(a[0]), "r"(a[1]), "r"(a[2]), "r"(a[3]), "r"(b0), "r"(b1));
}
__device__ __forceinline__ float sigf(float x)   { return __fdividef(1.f, 1.f + __expf(-x)); }
__device__ __forceinline__ float tanh_f(float x) { return 1.f - __fdividef(2.f, 1.f + __expf(2.f * x)); }

// gates += (Ahi+Alo) @ (Bhi+Blo)^T (dropping Alo*Blo). aHi/aLo = per-lane smem
// byte addrs for ldmatrix of mtile 0 (mtile 1 at +16*432B).
__device__ __forceinline__ void hgemm(const uint4* __restrict__ Bf, u32 aHi, u32 aLo,
                                      int w5, int lane, float (&acc)[2][5][4])
{
    const uint4* __restrict__ bp = Bf + w5 * 32 + lane;
#pragma unroll 1
    for (int s = 0; s < KSTEPS; s++) {
        u32 ah[2][4], al[2][4];
        u32 ko = (u32)(s * 32);          // 16 bf16 per step = 32 bytes
        ldsm4(ah[0], aHi + ko);
        ldsm4(ah[1], aHi + 16 * 432 + ko);
        ldsm4(al[0], aLo + ko);
        ldsm4(al[1], aLo + 16 * 432 + ko);
#pragma unroll
        for (int j = 0; j < 5; j++) {
            uint4 b = bp[(s * NTILES + j) * 32];
            mma16816(acc[0][j], ah[0], b.x, b.y);
            mma16816(acc[1][j], ah[1], b.x, b.y);
            mma16816(acc[0][j], al[0], b.x, b.y);
            mma16816(acc[1][j], al[1], b.x, b.y);
            mma16816(acc[0][j], ah[0], b.z, b.w);
            mma16816(acc[1][j], ah[1], b.z, b.w);
        }
    }
}

// acc init: bias + (optional) rank-1 wx * x[row]. C frag: c0,c1 = row gid cols
// (tig*2, tig*2+1); c2,c3 = row gid+8. Absolute row += mt*16.
__device__ __forceinline__ void acc_init(float (&acc)[2][5][4], const float* __restrict__ bias,
                                         const float* __restrict__ wx, const float* __restrict__ xrow,
                                         int w5, int lane)
{
    int gid = lane >> 2, tig = lane & 3;
#pragma unroll
    for (int mt = 0; mt < 2; mt++) {
        float xa = 0.f, xb = 0.f;
        if (xrow) { xa = xrow[mt * 16 + gid]; xb = xrow[mt * 16 + gid + 8]; }
#pragma unroll
        for (int j = 0; j < 5; j++) {
            int col0 = (w5 + j) * 8 + tig * 2;
            float b0v = bias[col0], b1v = bias[col0 + 1];
            if (xrow) {
                float w0 = wx[col0], w1 = wx[col0 + 1];
                acc[mt][j][0] = b0v + w0 * xa;
                acc[mt][j][1] = b1v + w1 * xa;
                acc[mt][j][2] = b0v + w0 * xb;
                acc[mt][j][3] = b1v + w1 * xb;
            } else {
                acc[mt][j][0] = b0v; acc[mt][j][1] = b1v;
                acc[mt][j][2] = b0v; acc[mt][j][3] = b1v;
            }
        }
    }
}

// Cell epilogue. Even tig holds (i,f), odd holds (g,o) of the same unit; swap
// via shfl_xor(1); even handles row gid, odd row gid+8. Writes c (fp32 smem)
// and h as bf16 hi/lo into the A buffers.
__device__ __forceinline__ void cell_epi(float (&acc)[2][5][4], float* __restrict__ cs,
                                         __nv_bfloat16* __restrict__ Ahi,
                                         __nv_bfloat16* __restrict__ Alo,
                                         int w5, int lane)
{
    int gid = lane >> 2, tig = lane & 3;
    bool ev = !(tig & 1);
#pragma unroll
    for (int mt = 0; mt < 2; mt++) {
#pragma unroll
        for (int j = 0; j < 5; j++) {
            int u = 2 * (w5 + j) + (tig >> 1);
            float o0 = __shfl_xor_sync(0xffffffffu, acc[mt][j][0], 1);
            float o1 = __shfl_xor_sync(0xffffffffu, acc[mt][j][1], 1);
            float o2 = __shfl_xor_sync(0xffffffffu, acc[mt][j][2], 1);
            float o3 = __shfl_xor_sync(0xffffffffu, acc[mt][j][3], 1);
            float gi, gf, gg, go;
            int row;
            if (ev) { gi = acc[mt][j][0]; gf = acc[mt][j][1]; gg = o0; go = o1; row = mt * 16 + gid; }
            else    { gi = o2; gf = o3; gg = acc[mt][j][2]; go = acc[mt][j][3]; row = mt * 16 + gid + 8; }
            float cv = cs[u * 32 + row];
            float cn = sigf(gf) * cv + sigf(gi) * tanh_f(gg);
            cs[u * 32 + row] = cn;
            float h = sigf(go) * tanh_f(cn);
            __nv_bfloat16 hh = __float2bfloat16(h);
            Ahi[row * ASTR + u] = hh;
            Alo[row * ASTR + u] = __float2bfloat16(h - __bfloat162float(hh));
        }
    }
}

// smem floats: Abufs 13824 | c0 6400 | c1 6400 | xs 4096 | vb 4800 | lin 200 | inp 32 | part 256
#define SMEM_FLOATS 36008

__global__ void __launch_bounds__(NTHR, 1)
lstm_kernel(const float* __restrict__ x, const float* __restrict__ linW,
            const float* __restrict__ linb, float* __restrict__ out)
{
    extern __shared__ float sm[];
    char* ab = reinterpret_cast<char*>(sm);      // 4 A buffers, 13824 B each
    __nv_bfloat16* h0hi = reinterpret_cast<__nv_bfloat16*>(ab);
    __nv_bfloat16* h0lo = reinterpret_cast<__nv_bfloat16*>(ab + ABUF_B);
    __nv_bfloat16* h1hi = reinterpret_cast<__nv_bfloat16*>(ab + 2 * ABUF_B);
    __nv_bfloat16* h1lo = reinterpret_cast<__nv_bfloat16*>(ab + 3 * ABUF_B);
    float* c0s   = sm + 13824;
    float* c1s   = sm + 20224;
    float* xs    = sm + 26624;    // [t=128][row=32]
    float* vb    = sm + 30720;    // 6 x 800, col-indexed
    float* lin_s = sm + 35520;    // 200
    float* inp_s = sm + 35720;    // 32
    float* part  = sm + 35752;    // 8 x 32

    const int tid  = threadIdx.x;
    const int lane = tid & 31;
    const int w5   = (tid >> 5) * 5;    // warp's first n-tile
    const int row0 = blockIdx.x * MCTA;

    // ldmatrix per-lane base: blk = which 8x8 (0:r0-7/k0-7 1:r8-15/k0-7 2:r0-7/k8+ 3:r8-15/k8+)
    const int blk = lane >> 3, rr = lane & 7;
    const u32 aoff = (u32)(((blk & 1) * 8 + rr) * 432 + (blk >> 1) * 16);
    const u32 a_h0hi = smem_u32(ab) + aoff;
    const u32 a_h0lo = a_h0hi + ABUF_B;
    const u32 a_h1hi = a_h0hi + 2 * ABUF_B;
    const u32 a_h1lo = a_h0hi + 3 * ABUF_B;

    // zero A buffers (incl. k padding) + c states; stage xs, vb, lin
    for (int i = tid; i < 26624; i += NTHR) sm[i] = 0.f;
    for (int i = tid; i < TLEN * MCTA; i += NTHR) {
        int t = i >> 5, r = i & 31;
        xs[i] = x[(row0 + r) * TLEN + t];
    }
    {
        const float* gv = &g_v[0][0];
        for (int i = tid; i < 6 * 800; i += NTHR) vb[i] = gv[i];
    }
    for (int i = tid; i < HID; i += NTHR) lin_s[i] = linW[i];
    __syncthreads();

    const float* wx0  = vb;
    const float* b0   = vb + 800;
    const float* b1   = vb + 1600;
    const float* dwx0 = vb + 2400;
    const float* db0  = vb + 3200;
    const float* db1  = vb + 4000;

    // ---------------- encoder: 128 steps ----------------
    for (int t = 0; t < TLEN; t++) {
        float acc[2][5][4];
        acc_init(acc, b0, wx0, xs + t * 32, w5, lane);
        hgemm(g_Bf[0], a_h0hi, a_h0lo, w5, lane, acc);
        __syncthreads();
        cell_epi(acc, c0s, h0hi, h0lo, w5, lane);
        __syncthreads();

        float accb[2][5][4];
        acc_init(accb, b1, (const float*)0, (const float*)0, w5, lane);
        hgemm(g_Bf[1], a_h0hi, a_h0lo, w5, lane, accb);   // input = new h0
        hgemm(g_Bf[2], a_h1hi, a_h1lo, w5, lane, accb);   // recurrence h1
        __syncthreads();
        cell_epi(accb, c1s, h1hi, h1lo, w5, lane);
        __syncthreads();
    }

    // decoder initial input = x[:, T-1]
    if (tid < MCTA) inp_s[tid] = xs[(TLEN - 1) * 32 + tid];
    __syncthreads();

    const float lb = linb[0];

    // ---------------- decoder: 64 steps ----------------
    for (int t = 0; t < OUTLEN; t++) {
        float acc[2][5][4];
        acc_init(acc, db0, dwx0, inp_s, w5, lane);
        hgemm(g_Bf[3], a_h0hi, a_h0lo, w5, lane, acc);
        __syncthreads();
        cell_epi(acc, c0s, h0hi, h0lo, w5, lane);
        __syncthreads();

        float accb[2][5][4];
        acc_init(accb, db1, (const float*)0, (const float*)0, w5, lane);
        hgemm(g_Bf[4], a_h0hi, a_h0lo, w5, lane, accb);   // input = new h0
        hgemm(g_Bf[5], a_h1hi, a_h1lo, w5, lane, accb);
        __syncthreads();
        cell_epi(accb, c1s, h1hi, h1lo, w5, lane);
        __syncthreads();

        // linear head: pred = h1 @ lin_W.T + lin_b (h1 = hi+lo)
        if (tid < 256) {
            int grp = tid >> 5, r = tid & 31;
            int ub = grp * 25;
            float s = 0.f;
#pragma unroll 5
            for (int u = 0; u < 25; u++) {
                int uu = ub + u;
                float hv = __bfloat162float(h1hi[r * ASTR + uu]) +
                           __bfloat162float(h1lo[r * ASTR + uu]);
                s += lin_s[uu] * hv;
            }
            part[grp * 32 + r] = s;
        }
        __syncthreads();
        if (tid < MCTA) {
            float s = lb;
#pragma unroll
            for (int g = 0; g < 8; g++) s += part[g * 32 + tid];
            out[(row0 + tid) * OUTLEN + t] = s;
            inp_s[tid] = s;
        }
        __syncthreads();
    }
}

extern "C" void kernel_launch(void* const* d_in, const int* in_sizes, int n_in,
                              void* d_out, int out_size)
{
    (void)in_sizes; (void)n_in; (void)out_size;
    const float* x     = (const float*)d_in[0];
    const float* eWih0 = (const float*)d_in[1];
    const float* eWhh0 = (const float*)d_in[2];
    const float* eb0   = (const float*)d_in[3];
    const float* eWih1 = (const float*)d_in[4];
    const float* eWhh1 = (const float*)d_in[5];
    const float* eb1   = (const float*)d_in[6];
    const float* dWih0 = (const float*)d_in[7];
    const float* dWhh0 = (const float*)d_in[8];
    const float* db0   = (const float*)d_in[9];
    const float* dWih1 = (const float*)d_in[10];
    const float* dWhh1 = (const float*)d_in[11];
    const float* db1   = (const float*)d_in[12];
    const float* linW  = (const float*)d_in[13];
    const float* linb  = (const float*)d_in[14];
    float* out = (float*)d_out;

    cudaFuncSetAttribute(lstm_kernel, cudaFuncAttributeMaxDynamicSharedMemorySize,
                         SMEM_FLOATS * (int)sizeof(float));

    prep_kernel<<<(FRAG_ELEMS + 255) / 256, 256>>>(eWhh0, eWih1, eWhh1, dWhh0, dWih1, dWhh1,
                                                   eWih0, eb0, eb1, dWih0, db0, db1);
    lstm_kernel<<<NBLK, NTHR, SMEM_FLOATS * (int)sizeof(float)>>>(x, linW, linb, out);
}